// round 14
// baseline (speedup 1.0000x reference)
#include <cuda_runtime.h>
#include <math.h>

#define SS 512
#define BB 64
#define II 256
#define HH 1024
#define BH (BB*HH)
#define NB 128          // persistent CTAs (single wave, < 148 SMs)
#define NT 8            // output columns per CTA
#define NTH 512         // threads per CTA (16 warps)
#define KW  64          // K-slice per warp
#define NWARP 16

typedef unsigned long long u64;

// packed f32x2 FMA: d = a*b + d (full fp32 precision, 2 lanes per instr)
#define FMA2(d, a, b) \
    asm("fma.rn.f32x2 %0, %1, %2, %0;" : "+l"(d) : "l"(a), "l"(b))

// ============================================================================
// Scratch: transposed h, double-buffered. hT[buf][k][m] (k-major, m contig).
// g_bar[t]     : count of CTAs that completed step t (epilogue WAR guard).
// g_flag[t][c] : CTA c finished writing its h_t columns (mainloop RAW guard).
// Zeroed per launch via cudaMemsetAsync.
// ============================================================================
__device__ __align__(16) float g_hT[2][HH * BB];
__device__ unsigned g_bar[SS];
__device__ unsigned g_flag[SS][NB];

// ============================================================================
// Kernel 1 (R11-proven scalar version): xproj = x @ Wx^T + bx -> out slabs.
// ============================================================================
__global__ __launch_bounds__(256) void xproj_kernel(
    const float* __restrict__ x, const float* __restrict__ Wx,
    const float* __restrict__ bx, float* __restrict__ out)
{
    __shared__ __align__(16) float xs[16][68];
    __shared__ __align__(16) float ws[16][68];
    const int mBase = blockIdx.y * 64;
    const int nBase = blockIdx.x * 64;
    const int tid = threadIdx.x;
    const int tx = tid & 15;
    const int ty = tid >> 4;
    const int r = tid >> 2;
    const int c = tid & 3;

    float acc[4][4] = {};

    for (int k0 = 0; k0 < II; k0 += 16) {
        float4 xa = *(const float4*)&x [(size_t)(mBase + r) * II + k0 + c * 4];
        float4 wa = *(const float4*)&Wx[(size_t)(nBase + r) * II + k0 + c * 4];
        __syncthreads();
        xs[c*4+0][r] = xa.x; xs[c*4+1][r] = xa.y; xs[c*4+2][r] = xa.z; xs[c*4+3][r] = xa.w;
        ws[c*4+0][r] = wa.x; ws[c*4+1][r] = wa.y; ws[c*4+2][r] = wa.z; ws[c*4+3][r] = wa.w;
        __syncthreads();
        #pragma unroll
        for (int kk = 0; kk < 16; kk++) {
            float4 a = *(const float4*)&xs[kk][ty * 4];
            float4 b = *(const float4*)&ws[kk][tx * 4];
            acc[0][0] += a.x*b.x; acc[0][1] += a.x*b.y; acc[0][2] += a.x*b.z; acc[0][3] += a.x*b.w;
            acc[1][0] += a.y*b.x; acc[1][1] += a.y*b.y; acc[1][2] += a.y*b.z; acc[1][3] += a.y*b.w;
            acc[2][0] += a.z*b.x; acc[2][1] += a.z*b.y; acc[2][2] += a.z*b.z; acc[2][3] += a.z*b.w;
            acc[3][0] += a.w*b.x; acc[3][1] += a.w*b.y; acc[3][2] += a.w*b.z; acc[3][3] += a.w*b.w;
        }
    }

    #pragma unroll
    for (int i = 0; i < 4; i++) {
        #pragma unroll
        for (int j = 0; j < 4; j++) {
            int row = mBase + ty * 4 + i;
            int col = nBase + tx * 4 + j;
            out[(size_t)row * HH + col] = acc[i][j] + bx[col];
        }
    }
}

// ============================================================================
// Persistent RNN kernel with LAGGED fine-grained sync.
//  - mainloop RAW: warp ks waits flags of its 8 producer CTAs (ks*8..ks*8+7)
//  - epilogue WAR: wait bar[t-1]==NB AFTER the mainloop (cost hidden)
//  - end of step: fence -> sync -> tid0 sets flag + arrives bar (NO spin)
// Math identical to R11 (FFMA2, KW=64, depth-8 LDG pipeline, packed red,
// exact tanhf).
// ============================================================================
__global__ __launch_bounds__(NTH) void rnn_persistent(
    const float* __restrict__ Wh, const float* __restrict__ bh,
    float* __restrict__ out)
{
    extern __shared__ __align__(16) float sm[];
    float* wsf2 = sm;                       // [1024][8][2] Wh dup-pairs (64 KB)
    u64*   red2 = (u64*)(sm + 16384);       // [16][256]    packed partials (32 KB)

    const int tid   = threadIdx.x;
    const int bid   = blockIdx.x;
    const int nBase = bid * NT;
    const int ks    = tid >> 5;             // warp = k-split group 0..15
    const int lane  = tid & 31;
    const int n_thr = lane & 1;
    const int m_thr = lane >> 1;
    const int k0    = ks * KW;

    // ---- one-time Wh slice preload, duplicated: wsf2[(k*8+n)*2 + {0,1}] ----
    #pragma unroll
    for (int j = 0; j < 4; j++) {
        int lin = tid + j * NTH;
        int n  = lin >> 8;
        int k4 = lin & 255;
        float4 w = *(const float4*)&Wh[(size_t)(nBase + n) * HH + k4 * 4];
        int b0 = ((k4*4+0)*8 + n)*2;  wsf2[b0]   = w.x; wsf2[b0+1] = w.x;
        int b1 = ((k4*4+1)*8 + n)*2;  wsf2[b1]   = w.y; wsf2[b1+1] = w.y;
        int b2 = ((k4*4+2)*8 + n)*2;  wsf2[b2]   = w.z; wsf2[b2+1] = w.z;
        int b3 = ((k4*4+3)*8 + n)*2;  wsf2[b3]   = w.w; wsf2[b3+1] = w.w;
    }

    // epilogue mapping
    const int eo_m  = tid >> 3;
    const int eo_n  = tid & 7;
    const int eo_mp = eo_m >> 1;
    const int eo_hf = eo_m & 1;
    const float bias = bh[nBase + eo_n];
    const size_t eo_idx = (size_t)eo_m * HH + nBase + eo_n;
    const int hT_idx = (nBase + eo_n) * BB + eo_m;
    const float* redf = (const float*)red2;
    const int red_off = (eo_mp * 8 + eo_n) * 2 + eo_hf;

    // ---- step 0: h0 = 0  =>  h_0 = tanh(xproj0 + bh); write out + hT[0] ----
    {
        float v = tanhf(out[eo_idx] + bias);
        out[eo_idx] = v;
        g_hT[0][hT_idx] = v;
    }
    __threadfence();
    __syncthreads();
    if (tid == 0) {
        volatile unsigned* f = &g_flag[0][bid];
        *f = 1u;
        atomicAdd(&g_bar[0], 1u);
    }

    // ---- steps 1..511 ----
    for (int t = 1; t < SS; t++) {
        const float* hT  = g_hT[(t - 1) & 1];
        float*       hTo = g_hT[t & 1];
        float*       hx  = out + (size_t)t * BH;

        // prefetch this thread's xproj term early (private; no hazard)
        float xp = __ldcg(&hx[eo_idx]);

        // --- fine-grained RAW wait: this warp's 8 producer CTAs for step t-1
        if (lane < 8) {
            volatile unsigned* f = &g_flag[t - 1][ks * 8 + lane];
            while (*f == 0u) { }
        }
        __syncwarp();

        u64 acc2[4][2] = {};
        const float* aBase = hT + (size_t)k0 * BB + m_thr * 4;
        const float* bBase = wsf2 + (k0 * 8 + n_thr * 4) * 2;

        ulonglong2 abuf[8];
        #pragma unroll
        for (int i = 0; i < 8; i++)
            abuf[i] = __ldcg((const ulonglong2*)(aBase + i * BB));

        #pragma unroll 8
        for (int kk = 0; kk < KW - 8; kk++) {
            ulonglong2 av = abuf[kk & 7];
            abuf[kk & 7] = __ldcg((const ulonglong2*)(aBase + (kk + 8) * BB));
            ulonglong2 b01 = *(const ulonglong2*)(bBase + kk * 16);
            ulonglong2 b23 = *(const ulonglong2*)(bBase + kk * 16 + 4);
            FMA2(acc2[0][0], av.x, b01.x); FMA2(acc2[0][1], av.y, b01.x);
            FMA2(acc2[1][0], av.x, b01.y); FMA2(acc2[1][1], av.y, b01.y);
            FMA2(acc2[2][0], av.x, b23.x); FMA2(acc2[2][1], av.y, b23.x);
            FMA2(acc2[3][0], av.x, b23.y); FMA2(acc2[3][1], av.y, b23.y);
        }
        #pragma unroll
        for (int kk = KW - 8; kk < KW; kk++) {
            ulonglong2 av = abuf[kk & 7];
            ulonglong2 b01 = *(const ulonglong2*)(bBase + kk * 16);
            ulonglong2 b23 = *(const ulonglong2*)(bBase + kk * 16 + 4);
            FMA2(acc2[0][0], av.x, b01.x); FMA2(acc2[0][1], av.y, b01.x);
            FMA2(acc2[1][0], av.x, b01.y); FMA2(acc2[1][1], av.y, b01.y);
            FMA2(acc2[2][0], av.x, b23.x); FMA2(acc2[2][1], av.y, b23.x);
            FMA2(acc2[3][0], av.x, b23.y); FMA2(acc2[3][1], av.y, b23.y);
        }

        // split-K reduction: packed-pair stores
        // (previous step's trailing __syncthreads guards red reuse)
        #pragma unroll
        for (int p = 0; p < 2; p++) {
            int base = ks * 256 + (m_thr * 2 + p) * 8 + n_thr * 4;
            ulonglong2 v01; v01.x = acc2[0][p]; v01.y = acc2[1][p];
            ulonglong2 v23; v23.x = acc2[2][p]; v23.y = acc2[3][p];
            *(ulonglong2*)&red2[base]     = v01;
            *(ulonglong2*)&red2[base + 2] = v23;
        }
        __syncthreads();

        // --- lagged WAR guard: all CTAs must have COMPLETED step t-1 before
        //     we overwrite buf(t) (= buf(t-2), read during step t-1).
        //     By now this wait is ~free (hidden behind our own mainloop).
        if (tid == 0) {
            volatile unsigned* p = &g_bar[t - 1];
            while (*p < NB) { }
        }
        __syncthreads();

        // final sum -> tanh -> write out slab + transposed h
        {
            float s = 0.f;
            #pragma unroll
            for (int p = 0; p < NWARP; p++) s += redf[p * 512 + red_off];
            float v = tanhf(s + bias + xp);
            hx[eo_idx] = v;
            hTo[hT_idx] = v;
        }

        // publish step t: fence -> sync -> flag + arrive (no spin)
        __threadfence();
        __syncthreads();
        if (tid == 0 && t < SS - 1) {
            volatile unsigned* f = &g_flag[t][bid];
            *f = 1u;
            atomicAdd(&g_bar[t], 1u);
        }
    }
}

// ============================================================================
// Launch: memset sync state -> xproj -> persistent RNN -> D2D h_last copy.
// ============================================================================
extern "C" void kernel_launch(void* const* d_in, const int* in_sizes, int n_in,
                              void* d_out, int out_size)
{
    const float* x  = (const float*)d_in[0];
    const float* Wx = (const float*)d_in[1];
    const float* bx = (const float*)d_in[2];
    const float* Wh = (const float*)d_in[3];
    const float* bh = (const float*)d_in[4];
    float* out = (float*)d_out;

    void* bar_ptr = nullptr;
    cudaGetSymbolAddress(&bar_ptr, g_bar);
    cudaMemsetAsync(bar_ptr, 0, SS * sizeof(unsigned));
    void* flag_ptr = nullptr;
    cudaGetSymbolAddress(&flag_ptr, g_flag);
    cudaMemsetAsync(flag_ptr, 0, SS * NB * sizeof(unsigned));

    const int smemBytes = 16384 * 4 + 16 * 256 * 8;   // 64 KB + 32 KB = 96 KB
    cudaFuncSetAttribute(rnn_persistent,
                         cudaFuncAttributeMaxDynamicSharedMemorySize, smemBytes);

    xproj_kernel<<<dim3(HH / 64, (SS * BB) / 64), 256>>>(x, Wx, bx, out);
    rnn_persistent<<<NB, NTH, smemBytes>>>(Wh, bh, out);

    cudaMemcpyAsync(out + (size_t)SS * BH, out + (size_t)(SS - 1) * BH,
                    (size_t)BH * sizeof(float), cudaMemcpyDeviceToDevice);
}

// round 15
// speedup vs baseline: 1.0829x; 1.0829x over previous
#include <cuda_runtime.h>
#include <math.h>

#define SS 512
#define BB 64
#define II 256
#define HH 1024
#define BH (BB*HH)
#define NB 128          // persistent CTAs (single wave, < 148 SMs)
#define NT 8            // output columns per CTA
#define NTH 512         // threads per CTA (16 warps)
#define KW  64          // K-slice per warp
#define NWARP 16

typedef unsigned long long u64;

// packed f32x2 FMA: d = a*b + d (full fp32 precision, 2 lanes per instr)
#define FMA2(d, a, b) \
    asm("fma.rn.f32x2 %0, %1, %2, %0;" : "+l"(d) : "l"(a), "l"(b))

// ============================================================================
// Scratch: transposed h, double-buffered. hT[buf][k][m] (k-major, m contig).
// Grid-barrier counters, zeroed per launch via cudaMemsetAsync.
// ============================================================================
__device__ __align__(16) float g_hT[2][HH * BB];
__device__ unsigned g_bar[SS];

// ============================================================================
// Kernel 1: xproj = x @ Wx^T + bx  (M=32768, N=1024, K=256) -> out slabs.
// FFMA2 with the recurrence-proven broadcast layout:
//   8 warps/CTA, warp w owns n-slice [w*8, w*8+8);
//   lanes = 16 m_thr x 2 n_thr, 4m x 4n per thread (2 m-pairs);
//   b staged as dup-pairs ws2[k][n][2] -> per-warp b loads = 2 distinct
//   16B addresses (broadcast, conflict-free);
//   a = xs[kk][m_thr*4] LDS.128, 16 distinct 16B (standard conflict-free).
// Inner iter: 3 LDS.128 + 8 FFMA2 (was 2 LDS.128 + 16 FFMA scalar).
// ============================================================================
__global__ __launch_bounds__(256) void xproj_kernel(
    const float* __restrict__ x, const float* __restrict__ Wx,
    const float* __restrict__ bx, float* __restrict__ out)
{
    __shared__ __align__(16) float xs[16][68];        // [k][m]
    __shared__ __align__(16) float ws2[16][64][2];    // [k][n][dup]
    const int mBase = blockIdx.y * 64;
    const int nBase = blockIdx.x * 64;
    const int tid  = threadIdx.x;
    const int w    = tid >> 5;          // warp 0..7 -> n-slice
    const int lane = tid & 31;
    const int n_thr = lane & 1;         // 0..1 (4 n each)
    const int m_thr = lane >> 1;        // 0..15 (4 m each = 2 m-pairs)
    const int r = tid >> 2;             // fill: row 0..63
    const int c = tid & 3;              // fill: float4 index 0..3

    u64 acc2[4][2] = {};                // [n][m-pair]

    for (int k0 = 0; k0 < II; k0 += 16) {
        float4 xa = *(const float4*)&x [(size_t)(mBase + r) * II + k0 + c * 4];
        float4 wa = *(const float4*)&Wx[(size_t)(nBase + r) * II + k0 + c * 4];
        __syncthreads();
        xs[c*4+0][r] = xa.x; xs[c*4+1][r] = xa.y; xs[c*4+2][r] = xa.z; xs[c*4+3][r] = xa.w;
        ws2[c*4+0][r][0] = wa.x; ws2[c*4+0][r][1] = wa.x;
        ws2[c*4+1][r][0] = wa.y; ws2[c*4+1][r][1] = wa.y;
        ws2[c*4+2][r][0] = wa.z; ws2[c*4+2][r][1] = wa.z;
        ws2[c*4+3][r][0] = wa.w; ws2[c*4+3][r][1] = wa.w;
        __syncthreads();
        #pragma unroll
        for (int kk = 0; kk < 16; kk++) {
            ulonglong2 av  = *(const ulonglong2*)&xs[kk][m_thr * 4];
            const float* bb = &ws2[kk][w * 8 + n_thr * 4][0];
            ulonglong2 b01 = *(const ulonglong2*)bb;        // dups for n j=0,1
            ulonglong2 b23 = *(const ulonglong2*)(bb + 4);  // dups for n j=2,3
            FMA2(acc2[0][0], av.x, b01.x); FMA2(acc2[0][1], av.y, b01.x);
            FMA2(acc2[1][0], av.x, b01.y); FMA2(acc2[1][1], av.y, b01.y);
            FMA2(acc2[2][0], av.x, b23.x); FMA2(acc2[2][1], av.y, b23.x);
            FMA2(acc2[3][0], av.x, b23.y); FMA2(acc2[3][1], av.y, b23.y);
        }
    }

    #pragma unroll
    for (int j = 0; j < 4; j++) {
        int col = nBase + w * 8 + n_thr * 4 + j;
        float bxv = bx[col];
        #pragma unroll
        for (int p = 0; p < 2; p++) {
            float lo = __uint_as_float((unsigned)(acc2[j][p] & 0xFFFFFFFFu));
            float hi = __uint_as_float((unsigned)(acc2[j][p] >> 32));
            int row = mBase + m_thr * 4 + 2 * p;
            out[(size_t)row * HH + col]       = lo + bxv;
            out[(size_t)(row + 1) * HH + col] = hi + bxv;
        }
    }
}

// ============================================================================
// Persistent RNN kernel (R11-proven, byte-identical): all 512 steps.
// 16 warps x (16 m_thr x 2 n_thr), 4m x 4n per thread (m-packed FFMA2),
// K=64 per warp, LDG depth-8 pipeline, packed-u64 reduction, exact tanhf,
// atomicAdd grid barrier.
// ============================================================================
__global__ __launch_bounds__(NTH) void rnn_persistent(
    const float* __restrict__ Wh, const float* __restrict__ bh,
    float* __restrict__ out)
{
    extern __shared__ __align__(16) float sm[];
    float* wsf2 = sm;                       // [1024][8][2] Wh dup-pairs (64 KB)
    u64*   red2 = (u64*)(sm + 16384);       // [16][256]    packed partials (32 KB)

    const int tid   = threadIdx.x;
    const int nBase = blockIdx.x * NT;
    const int ks    = tid >> 5;             // warp = k-split group 0..15
    const int lane  = tid & 31;
    const int n_thr = lane & 1;             // 0..1 (4 n each)
    const int m_thr = lane >> 1;            // 0..15 (4 m each = 2 m-pairs)
    const int k0    = ks * KW;              // this warp's K range (64 wide)

    // ---- one-time Wh slice preload, duplicated: wsf2[(k*8+n)*2 + {0,1}] ----
    #pragma unroll
    for (int j = 0; j < 4; j++) {
        int lin = tid + j * NTH;            // float4 index 0..2047
        int n  = lin >> 8;                  // 0..7
        int k4 = lin & 255;                 // 0..255
        float4 w = *(const float4*)&Wh[(size_t)(nBase + n) * HH + k4 * 4];
        int b0 = ((k4*4+0)*8 + n)*2;  wsf2[b0]   = w.x; wsf2[b0+1] = w.x;
        int b1 = ((k4*4+1)*8 + n)*2;  wsf2[b1]   = w.y; wsf2[b1+1] = w.y;
        int b2 = ((k4*4+2)*8 + n)*2;  wsf2[b2]   = w.z; wsf2[b2+1] = w.z;
        int b3 = ((k4*4+3)*8 + n)*2;  wsf2[b3]   = w.w; wsf2[b3+1] = w.w;
    }

    // epilogue mapping: o = tid -> (m = o>>3, n_local = o&7)
    const int eo_m  = tid >> 3;
    const int eo_n  = tid & 7;
    const int eo_mp = eo_m >> 1;            // m-pair index
    const int eo_hf = eo_m & 1;             // which half of the pair
    const float bias = bh[nBase + eo_n];
    const size_t eo_idx = (size_t)eo_m * HH + nBase + eo_n;
    const int hT_idx = (nBase + eo_n) * BB + eo_m;
    // scalar view of packed partials for the final sum
    const float* redf = (const float*)red2;
    const int red_off = (eo_mp * 8 + eo_n) * 2 + eo_hf;

    // ---- step 0: h0 = 0  =>  h_0 = tanh(xproj0 + bh); write out + hT[0] ----
    {
        float v = tanhf(out[eo_idx] + bias);
        out[eo_idx] = v;
        g_hT[0][hT_idx] = v;
    }

    __threadfence();
    __syncthreads();
    if (tid == 0) {
        unsigned old = atomicAdd(&g_bar[0], 1u);
        if (old != NB - 1) {
            volatile unsigned* p = &g_bar[0];
            while (*p < NB) { }
        }
    }
    __syncthreads();

    // ---- steps 1..511 ----
    for (int t = 1; t < SS; t++) {
        const float* hT  = g_hT[(t - 1) & 1];
        float*       hTo = g_hT[t & 1];
        float*       hx  = out + (size_t)t * BH;

        // prefetch this thread's xproj term early (hides DRAM/L2 latency)
        float xp = __ldcg(&hx[eo_idx]);

        // acc2[n][p]: n = 0..3 (col n_thr*4+n), p = m-pair (m = m_thr*4+2p)
        u64 acc2[4][2] = {};

        const float* aBase = hT + (size_t)k0 * BB + m_thr * 4;
        const float* bBase = wsf2 + (k0 * 8 + n_thr * 4) * 2;

        // register pipeline depth 8 (covers L2 latency even at ramp)
        ulonglong2 abuf[8];
        #pragma unroll
        for (int i = 0; i < 8; i++)
            abuf[i] = __ldcg((const ulonglong2*)(aBase + i * BB));

        #pragma unroll 8
        for (int kk = 0; kk < KW - 8; kk++) {
            ulonglong2 av = abuf[kk & 7];
            abuf[kk & 7] = __ldcg((const ulonglong2*)(aBase + (kk + 8) * BB));
            ulonglong2 b01 = *(const ulonglong2*)(bBase + kk * 16);
            ulonglong2 b23 = *(const ulonglong2*)(bBase + kk * 16 + 4);
            FMA2(acc2[0][0], av.x, b01.x); FMA2(acc2[0][1], av.y, b01.x);
            FMA2(acc2[1][0], av.x, b01.y); FMA2(acc2[1][1], av.y, b01.y);
            FMA2(acc2[2][0], av.x, b23.x); FMA2(acc2[2][1], av.y, b23.x);
            FMA2(acc2[3][0], av.x, b23.y); FMA2(acc2[3][1], av.y, b23.y);
        }
        #pragma unroll
        for (int kk = KW - 8; kk < KW; kk++) {
            ulonglong2 av = abuf[kk & 7];
            ulonglong2 b01 = *(const ulonglong2*)(bBase + kk * 16);
            ulonglong2 b23 = *(const ulonglong2*)(bBase + kk * 16 + 4);
            FMA2(acc2[0][0], av.x, b01.x); FMA2(acc2[0][1], av.y, b01.x);
            FMA2(acc2[1][0], av.x, b01.y); FMA2(acc2[1][1], av.y, b01.y);
            FMA2(acc2[2][0], av.x, b23.x); FMA2(acc2[2][1], av.y, b23.x);
            FMA2(acc2[3][0], av.x, b23.y); FMA2(acc2[3][1], av.y, b23.y);
        }

        // split-K reduction: store packed pairs (2x STS.128 per thread)
        // layout: red2[ks*256 + m_pair*8 + n]  where m_pair = m_thr*2+p
        __syncthreads();
        #pragma unroll
        for (int p = 0; p < 2; p++) {
            int base = ks * 256 + (m_thr * 2 + p) * 8 + n_thr * 4;
            ulonglong2 v01; v01.x = acc2[0][p]; v01.y = acc2[1][p];
            ulonglong2 v23; v23.x = acc2[2][p]; v23.y = acc2[3][p];
            *(ulonglong2*)&red2[base]     = v01;
            *(ulonglong2*)&red2[base + 2] = v23;
        }
        __syncthreads();

        // final sum: 512 threads, one output each, scalar reads of packed red
        {
            float s = 0.f;
            #pragma unroll
            for (int p = 0; p < NWARP; p++) s += redf[p * 512 + red_off];
            float v = tanhf(s + bias + xp);
            hx[eo_idx] = v;
            hTo[hT_idx] = v;
        }

        // grid barrier between steps (none after the last step)
        if (t < SS - 1) {
            __threadfence();
            __syncthreads();
            if (tid == 0) {
                unsigned old = atomicAdd(&g_bar[t], 1u);
                if (old != NB - 1) {
                    volatile unsigned* p = &g_bar[t];
                    while (*p < NB) { }
                }
            }
            __syncthreads();
        }
    }
}

// ============================================================================
// Launch: memset barriers -> xproj -> persistent RNN -> D2D h_last copy.
// ============================================================================
extern "C" void kernel_launch(void* const* d_in, const int* in_sizes, int n_in,
                              void* d_out, int out_size)
{
    const float* x  = (const float*)d_in[0];
    const float* Wx = (const float*)d_in[1];
    const float* bx = (const float*)d_in[2];
    const float* Wh = (const float*)d_in[3];
    const float* bh = (const float*)d_in[4];
    float* out = (float*)d_out;

    void* bar_ptr = nullptr;
    cudaGetSymbolAddress(&bar_ptr, g_bar);
    cudaMemsetAsync(bar_ptr, 0, SS * sizeof(unsigned));

    const int smemBytes = 16384 * 4 + 16 * 256 * 8;   // 64 KB + 32 KB = 96 KB
    cudaFuncSetAttribute(rnn_persistent,
                         cudaFuncAttributeMaxDynamicSharedMemorySize, smemBytes);

    xproj_kernel<<<dim3(HH / 64, (SS * BB) / 64), 256>>>(x, Wx, bx, out);
    rnn_persistent<<<NB, NTH, smemBytes>>>(Wh, bh, out);

    cudaMemcpyAsync(out + (size_t)SS * BH, out + (size_t)(SS - 1) * BH,
                    (size_t)BH * sizeof(float), cudaMemcpyDeviceToDevice);
}

// round 16
// speedup vs baseline: 1.8102x; 1.6717x over previous
#include <cuda_runtime.h>
#include <math.h>

#define SS 512
#define BB 64
#define II 256
#define HH 1024
#define BH (BB*HH)
#define NB 128          // persistent CTAs (single wave, < 148 SMs)
#define NT 8            // output columns per CTA
#define NTH 512         // threads per CTA (16 warps)
#define KW  64          // K-slice per warp
#define NWARP 16

typedef unsigned long long u64;

// packed f32x2 FMA: d = a*b + d (full fp32 precision, 2 lanes per instr)
#define FMA2(d, a, b) \
    asm("fma.rn.f32x2 %0, %1, %2, %0;" : "+l"(d) : "l"(a), "l"(b))

// ============================================================================
// Scratch: transposed h, double-buffered. hT[buf][k][m] (k-major, m contig).
// Grid-barrier counters, zeroed per launch via cudaMemsetAsync.
// ============================================================================
__device__ __align__(16) float g_hT[2][HH * BB];
__device__ unsigned g_bar[SS];

// ============================================================================
// Kernel 1 (R11-proven scalar version): xproj = x @ Wx^T + bx -> out slabs.
// Measured at ~91% of the scalar-FMA issue floor; do not touch.
// ============================================================================
__global__ __launch_bounds__(256) void xproj_kernel(
    const float* __restrict__ x, const float* __restrict__ Wx,
    const float* __restrict__ bx, float* __restrict__ out)
{
    __shared__ __align__(16) float xs[16][68];
    __shared__ __align__(16) float ws[16][68];
    const int mBase = blockIdx.y * 64;
    const int nBase = blockIdx.x * 64;
    const int tid = threadIdx.x;
    const int tx = tid & 15;
    const int ty = tid >> 4;
    const int r = tid >> 2;
    const int c = tid & 3;

    float acc[4][4] = {};

    for (int k0 = 0; k0 < II; k0 += 16) {
        float4 xa = *(const float4*)&x [(size_t)(mBase + r) * II + k0 + c * 4];
        float4 wa = *(const float4*)&Wx[(size_t)(nBase + r) * II + k0 + c * 4];
        __syncthreads();
        xs[c*4+0][r] = xa.x; xs[c*4+1][r] = xa.y; xs[c*4+2][r] = xa.z; xs[c*4+3][r] = xa.w;
        ws[c*4+0][r] = wa.x; ws[c*4+1][r] = wa.y; ws[c*4+2][r] = wa.z; ws[c*4+3][r] = wa.w;
        __syncthreads();
        #pragma unroll
        for (int kk = 0; kk < 16; kk++) {
            float4 a = *(const float4*)&xs[kk][ty * 4];
            float4 b = *(const float4*)&ws[kk][tx * 4];
            acc[0][0] += a.x*b.x; acc[0][1] += a.x*b.y; acc[0][2] += a.x*b.z; acc[0][3] += a.x*b.w;
            acc[1][0] += a.y*b.x; acc[1][1] += a.y*b.y; acc[1][2] += a.y*b.z; acc[1][3] += a.y*b.w;
            acc[2][0] += a.z*b.x; acc[2][1] += a.z*b.y; acc[2][2] += a.z*b.z; acc[2][3] += a.z*b.w;
            acc[3][0] += a.w*b.x; acc[3][1] += a.w*b.y; acc[3][2] += a.w*b.z; acc[3][3] += a.w*b.w;
        }
    }

    #pragma unroll
    for (int i = 0; i < 4; i++) {
        #pragma unroll
        for (int j = 0; j < 4; j++) {
            int row = mBase + ty * 4 + i;
            int col = nBase + tx * 4 + j;
            out[(size_t)row * HH + col] = acc[i][j] + bx[col];
        }
    }
}

// ============================================================================
// Persistent RNN kernel (R11 + double-buffered reduction scratch).
// 16 warps x (16 m_thr x 2 n_thr), 4m x 4n per thread (m-packed FFMA2),
// K=64 per warp, LDG depth-8 pipeline, packed-u64 reduction, exact tanhf,
// atomicAdd grid barrier.
// redA/redB alternate by step parity: the buffer written at step t was last
// read at step t-2, separated by two inter-step __syncthreads -> the
// pre-store sync of R11 is provably unnecessary and removed.
// ============================================================================
__global__ __launch_bounds__(NTH) void rnn_persistent(
    const float* __restrict__ Wh, const float* __restrict__ bh,
    float* __restrict__ out)
{
    extern __shared__ __align__(16) float sm[];
    float* wsf2 = sm;                        // [1024][8][2] Wh dup-pairs (64 KB)
    u64*   redA = (u64*)(sm + 16384);        // [16][256] packed partials (32 KB)
    u64*   redB = (u64*)(sm + 16384 + 8192); // second buffer (32 KB)

    const int tid   = threadIdx.x;
    const int nBase = blockIdx.x * NT;
    const int ks    = tid >> 5;              // warp = k-split group 0..15
    const int lane  = tid & 31;
    const int n_thr = lane & 1;              // 0..1 (4 n each)
    const int m_thr = lane >> 1;             // 0..15 (4 m each = 2 m-pairs)
    const int k0    = ks * KW;               // this warp's K range (64 wide)

    // ---- one-time Wh slice preload, duplicated: wsf2[(k*8+n)*2 + {0,1}] ----
    #pragma unroll
    for (int j = 0; j < 4; j++) {
        int lin = tid + j * NTH;             // float4 index 0..2047
        int n  = lin >> 8;                   // 0..7
        int k4 = lin & 255;                  // 0..255
        float4 w = *(const float4*)&Wh[(size_t)(nBase + n) * HH + k4 * 4];
        int b0 = ((k4*4+0)*8 + n)*2;  wsf2[b0]   = w.x; wsf2[b0+1] = w.x;
        int b1 = ((k4*4+1)*8 + n)*2;  wsf2[b1]   = w.y; wsf2[b1+1] = w.y;
        int b2 = ((k4*4+2)*8 + n)*2;  wsf2[b2]   = w.z; wsf2[b2+1] = w.z;
        int b3 = ((k4*4+3)*8 + n)*2;  wsf2[b3]   = w.w; wsf2[b3+1] = w.w;
    }

    // epilogue mapping: o = tid -> (m = o>>3, n_local = o&7)
    const int eo_m  = tid >> 3;
    const int eo_n  = tid & 7;
    const int eo_mp = eo_m >> 1;             // m-pair index
    const int eo_hf = eo_m & 1;              // which half of the pair
    const float bias = bh[nBase + eo_n];
    const size_t eo_idx = (size_t)eo_m * HH + nBase + eo_n;
    const int hT_idx = (nBase + eo_n) * BB + eo_m;
    const int red_off = (eo_mp * 8 + eo_n) * 2 + eo_hf;

    // ---- step 0: h0 = 0  =>  h_0 = tanh(xproj0 + bh); write out + hT[0] ----
    {
        float v = tanhf(out[eo_idx] + bias);
        out[eo_idx] = v;
        g_hT[0][hT_idx] = v;
    }

    __threadfence();
    __syncthreads();
    if (tid == 0) {
        unsigned old = atomicAdd(&g_bar[0], 1u);
        if (old != NB - 1) {
            volatile unsigned* p = &g_bar[0];
            while (*p < NB) { }
        }
    }
    __syncthreads();

    // ---- steps 1..511 ----
    for (int t = 1; t < SS; t++) {
        const float* hT  = g_hT[(t - 1) & 1];
        float*       hTo = g_hT[t & 1];
        float*       hx  = out + (size_t)t * BH;
        u64*         red2 = (t & 1) ? redB : redA;
        const float* redf = (const float*)red2;

        // prefetch this thread's xproj term early (hides DRAM/L2 latency)
        float xp = __ldcg(&hx[eo_idx]);

        // acc2[n][p]: n = 0..3 (col n_thr*4+n), p = m-pair (m = m_thr*4+2p)
        u64 acc2[4][2] = {};

        const float* aBase = hT + (size_t)k0 * BB + m_thr * 4;
        const float* bBase = wsf2 + (k0 * 8 + n_thr * 4) * 2;

        // register pipeline depth 8 (covers L2 latency even at ramp)
        ulonglong2 abuf[8];
        #pragma unroll
        for (int i = 0; i < 8; i++)
            abuf[i] = __ldcg((const ulonglong2*)(aBase + i * BB));

        #pragma unroll 8
        for (int kk = 0; kk < KW - 8; kk++) {
            ulonglong2 av = abuf[kk & 7];
            abuf[kk & 7] = __ldcg((const ulonglong2*)(aBase + (kk + 8) * BB));
            ulonglong2 b01 = *(const ulonglong2*)(bBase + kk * 16);
            ulonglong2 b23 = *(const ulonglong2*)(bBase + kk * 16 + 4);
            FMA2(acc2[0][0], av.x, b01.x); FMA2(acc2[0][1], av.y, b01.x);
            FMA2(acc2[1][0], av.x, b01.y); FMA2(acc2[1][1], av.y, b01.y);
            FMA2(acc2[2][0], av.x, b23.x); FMA2(acc2[2][1], av.y, b23.x);
            FMA2(acc2[3][0], av.x, b23.y); FMA2(acc2[3][1], av.y, b23.y);
        }
        #pragma unroll
        for (int kk = KW - 8; kk < KW; kk++) {
            ulonglong2 av = abuf[kk & 7];
            ulonglong2 b01 = *(const ulonglong2*)(bBase + kk * 16);
            ulonglong2 b23 = *(const ulonglong2*)(bBase + kk * 16 + 4);
            FMA2(acc2[0][0], av.x, b01.x); FMA2(acc2[0][1], av.y, b01.x);
            FMA2(acc2[1][0], av.x, b01.y); FMA2(acc2[1][1], av.y, b01.y);
            FMA2(acc2[2][0], av.x, b23.x); FMA2(acc2[2][1], av.y, b23.x);
            FMA2(acc2[3][0], av.x, b23.y); FMA2(acc2[3][1], av.y, b23.y);
        }

        // split-K reduction: packed-pair stores, NO pre-store sync needed
        // (this buffer was last read at step t-2; two barriers separate us)
        #pragma unroll
        for (int p = 0; p < 2; p++) {
            int base = ks * 256 + (m_thr * 2 + p) * 8 + n_thr * 4;
            ulonglong2 v01; v01.x = acc2[0][p]; v01.y = acc2[1][p];
            ulonglong2 v23; v23.x = acc2[2][p]; v23.y = acc2[3][p];
            *(ulonglong2*)&red2[base]     = v01;
            *(ulonglong2*)&red2[base + 2] = v23;
        }
        __syncthreads();

        // final sum: 512 threads, one output each, scalar reads of packed red
        {
            float s = 0.f;
            #pragma unroll
            for (int p = 0; p < NWARP; p++) s += redf[p * 512 + red_off];
            float v = tanhf(s + bias + xp);
            hx[eo_idx] = v;
            hTo[hT_idx] = v;
        }

        // grid barrier between steps (none after the last step)
        if (t < SS - 1) {
            __threadfence();
            __syncthreads();
            if (tid == 0) {
                unsigned old = atomicAdd(&g_bar[t], 1u);
                if (old != NB - 1) {
                    volatile unsigned* p = &g_bar[t];
                    while (*p < NB) { }
                }
            }
            __syncthreads();
        }
    }
}

// ============================================================================
// Launch: memset barriers -> xproj -> persistent RNN -> D2D h_last copy.
// ============================================================================
extern "C" void kernel_launch(void* const* d_in, const int* in_sizes, int n_in,
                              void* d_out, int out_size)
{
    const float* x  = (const float*)d_in[0];
    const float* Wx = (const float*)d_in[1];
    const float* bx = (const float*)d_in[2];
    const float* Wh = (const float*)d_in[3];
    const float* bh = (const float*)d_in[4];
    float* out = (float*)d_out;

    void* bar_ptr = nullptr;
    cudaGetSymbolAddress(&bar_ptr, g_bar);
    cudaMemsetAsync(bar_ptr, 0, SS * sizeof(unsigned));

    const int smemBytes = 16384 * 4 + 2 * 16 * 256 * 8;   // 64 KB + 64 KB = 128 KB
    cudaFuncSetAttribute(rnn_persistent,
                         cudaFuncAttributeMaxDynamicSharedMemorySize, smemBytes);

    xproj_kernel<<<dim3(HH / 64, (SS * BB) / 64), 256>>>(x, Wx, bx, out);
    rnn_persistent<<<NB, NTH, smemBytes>>>(Wh, bh, out);

    cudaMemcpyAsync(out + (size_t)SS * BH, out + (size_t)(SS - 1) * BH,
                    (size_t)BH * sizeof(float), cudaMemcpyDeviceToDevice);
}

// round 17
// speedup vs baseline: 1.9236x; 1.0627x over previous
#include <cuda_runtime.h>
#include <math.h>

#define SS 512
#define BB 64
#define II 256
#define HH 1024
#define BH (BB*HH)
#define NB 128          // persistent CTAs (single wave, < 148 SMs)
#define NT 8            // output columns per CTA
#define NTH 512         // threads per CTA (16 warps)
#define KW  64          // K-slice per warp
#define NWARP 16

typedef unsigned long long u64;

// packed f32x2 ops (full fp32 precision, 2 lanes per instr)
#define FMA2(d, a, b) \
    asm("fma.rn.f32x2 %0, %1, %2, %0;" : "+l"(d) : "l"(a), "l"(b))
#define ADD2(d, a) \
    asm("add.rn.f32x2 %0, %0, %1;" : "+l"(d) : "l"(a))

// ============================================================================
// Scratch: transposed h, double-buffered. hT[buf][k][m] (k-major, m contig).
// Grid-barrier counters, zeroed per launch via cudaMemsetAsync.
// ============================================================================
__device__ __align__(16) float g_hT[2][HH * BB];
__device__ unsigned g_bar[SS];

// ============================================================================
// Kernel 1 (R11-proven scalar version): xproj = x @ Wx^T + bx -> out slabs.
// Measured at ~91% of the scalar-FMA issue floor; do not touch.
// ============================================================================
__global__ __launch_bounds__(256) void xproj_kernel(
    const float* __restrict__ x, const float* __restrict__ Wx,
    const float* __restrict__ bx, float* __restrict__ out)
{
    __shared__ __align__(16) float xs[16][68];
    __shared__ __align__(16) float ws[16][68];
    const int mBase = blockIdx.y * 64;
    const int nBase = blockIdx.x * 64;
    const int tid = threadIdx.x;
    const int tx = tid & 15;
    const int ty = tid >> 4;
    const int r = tid >> 2;
    const int c = tid & 3;

    float acc[4][4] = {};

    for (int k0 = 0; k0 < II; k0 += 16) {
        float4 xa = *(const float4*)&x [(size_t)(mBase + r) * II + k0 + c * 4];
        float4 wa = *(const float4*)&Wx[(size_t)(nBase + r) * II + k0 + c * 4];
        __syncthreads();
        xs[c*4+0][r] = xa.x; xs[c*4+1][r] = xa.y; xs[c*4+2][r] = xa.z; xs[c*4+3][r] = xa.w;
        ws[c*4+0][r] = wa.x; ws[c*4+1][r] = wa.y; ws[c*4+2][r] = wa.z; ws[c*4+3][r] = wa.w;
        __syncthreads();
        #pragma unroll
        for (int kk = 0; kk < 16; kk++) {
            float4 a = *(const float4*)&xs[kk][ty * 4];
            float4 b = *(const float4*)&ws[kk][tx * 4];
            acc[0][0] += a.x*b.x; acc[0][1] += a.x*b.y; acc[0][2] += a.x*b.z; acc[0][3] += a.x*b.w;
            acc[1][0] += a.y*b.x; acc[1][1] += a.y*b.y; acc[1][2] += a.y*b.z; acc[1][3] += a.y*b.w;
            acc[2][0] += a.z*b.x; acc[2][1] += a.z*b.y; acc[2][2] += a.z*b.z; acc[2][3] += a.z*b.w;
            acc[3][0] += a.w*b.x; acc[3][1] += a.w*b.y; acc[3][2] += a.w*b.z; acc[3][3] += a.w*b.w;
        }
    }

    #pragma unroll
    for (int i = 0; i < 4; i++) {
        #pragma unroll
        for (int j = 0; j < 4; j++) {
            int row = mBase + ty * 4 + i;
            int col = nBase + tx * 4 + j;
            out[(size_t)row * HH + col] = acc[i][j] + bx[col];
        }
    }
}

// ============================================================================
// Persistent RNN kernel (R16 + pair-packed epilogue).
// Mainloop identical to R16. Epilogue: 256 threads own one m-pair each;
// partial sum via LDS.64 + add.f32x2 (same p-order => bit-identical),
// hTo written as STG.64 (m contiguous in hT).
// ============================================================================
__global__ __launch_bounds__(NTH) void rnn_persistent(
    const float* __restrict__ Wh, const float* __restrict__ bh,
    float* __restrict__ out)
{
    extern __shared__ __align__(16) float sm[];
    float* wsf2 = sm;                        // [1024][8][2] Wh dup-pairs (64 KB)
    u64*   redA = (u64*)(sm + 16384);        // [16][256] packed partials (32 KB)
    u64*   redB = (u64*)(sm + 16384 + 8192); // second buffer (32 KB)

    const int tid   = threadIdx.x;
    const int nBase = blockIdx.x * NT;
    const int ks    = tid >> 5;              // warp = k-split group 0..15
    const int lane  = tid & 31;
    const int n_thr = lane & 1;              // 0..1 (4 n each)
    const int m_thr = lane >> 1;             // 0..15 (4 m each = 2 m-pairs)
    const int k0    = ks * KW;               // this warp's K range (64 wide)

    // ---- one-time Wh slice preload, duplicated: wsf2[(k*8+n)*2 + {0,1}] ----
    #pragma unroll
    for (int j = 0; j < 4; j++) {
        int lin = tid + j * NTH;             // float4 index 0..2047
        int n  = lin >> 8;                   // 0..7
        int k4 = lin & 255;                  // 0..255
        float4 w = *(const float4*)&Wh[(size_t)(nBase + n) * HH + k4 * 4];
        int b0 = ((k4*4+0)*8 + n)*2;  wsf2[b0]   = w.x; wsf2[b0+1] = w.x;
        int b1 = ((k4*4+1)*8 + n)*2;  wsf2[b1]   = w.y; wsf2[b1+1] = w.y;
        int b2 = ((k4*4+2)*8 + n)*2;  wsf2[b2]   = w.z; wsf2[b2+1] = w.z;
        int b3 = ((k4*4+3)*8 + n)*2;  wsf2[b3]   = w.w; wsf2[b3+1] = w.w;
    }

    // pair-packed epilogue mapping (tid < 256): one m-pair per thread
    const int ep_mp = tid >> 3;              // m-pair 0..31 (m = 2*mp, 2*mp+1)
    const int ep_n  = tid & 7;               // 0..7
    const int ep_m0 = ep_mp * 2;
    const float bias = bh[nBase + ep_n];                       // valid tid<256 use
    const size_t ep_idx0 = (size_t)ep_m0 * HH + nBase + ep_n;  // row m0
    const size_t ep_idx1 = ep_idx0 + HH;                       // row m0+1
    const int ep_hT = (nBase + ep_n) * BB + ep_m0;             // STG.64 target
    const int ep_red = ep_mp * 8 + ep_n;                       // u64 index in red

    // ---- step 0: h0 = 0  =>  h_0 = tanh(xproj0 + bh); write out + hT[0] ----
    if (tid < 256) {
        float v0 = tanhf(out[ep_idx0] + bias);
        float v1 = tanhf(out[ep_idx1] + bias);
        out[ep_idx0] = v0;
        out[ep_idx1] = v1;
        float2 hv; hv.x = v0; hv.y = v1;
        *(float2*)&g_hT[0][ep_hT] = hv;
    }

    __threadfence();
    __syncthreads();
    if (tid == 0) {
        unsigned old = atomicAdd(&g_bar[0], 1u);
        if (old != NB - 1) {
            volatile unsigned* p = &g_bar[0];
            while (*p < NB) { }
        }
    }
    __syncthreads();

    // ---- steps 1..511 ----
    for (int t = 1; t < SS; t++) {
        const float* hT  = g_hT[(t - 1) & 1];
        float*       hTo = g_hT[t & 1];
        float*       hx  = out + (size_t)t * BH;
        u64*         red2 = (t & 1) ? redB : redA;

        // prefetch this thread's xproj terms early (hides DRAM/L2 latency)
        float xp0 = 0.f, xp1 = 0.f;
        if (tid < 256) {
            xp0 = __ldcg(&hx[ep_idx0]);
            xp1 = __ldcg(&hx[ep_idx1]);
        }

        // acc2[n][p]: n = 0..3 (col n_thr*4+n), p = m-pair (m = m_thr*4+2p)
        u64 acc2[4][2] = {};

        const float* aBase = hT + (size_t)k0 * BB + m_thr * 4;
        const float* bBase = wsf2 + (k0 * 8 + n_thr * 4) * 2;

        // register pipeline depth 8 (covers L2 latency even at ramp)
        ulonglong2 abuf[8];
        #pragma unroll
        for (int i = 0; i < 8; i++)
            abuf[i] = __ldcg((const ulonglong2*)(aBase + i * BB));

        #pragma unroll 8
        for (int kk = 0; kk < KW - 8; kk++) {
            ulonglong2 av = abuf[kk & 7];
            abuf[kk & 7] = __ldcg((const ulonglong2*)(aBase + (kk + 8) * BB));
            ulonglong2 b01 = *(const ulonglong2*)(bBase + kk * 16);
            ulonglong2 b23 = *(const ulonglong2*)(bBase + kk * 16 + 4);
            FMA2(acc2[0][0], av.x, b01.x); FMA2(acc2[0][1], av.y, b01.x);
            FMA2(acc2[1][0], av.x, b01.y); FMA2(acc2[1][1], av.y, b01.y);
            FMA2(acc2[2][0], av.x, b23.x); FMA2(acc2[2][1], av.y, b23.x);
            FMA2(acc2[3][0], av.x, b23.y); FMA2(acc2[3][1], av.y, b23.y);
        }
        #pragma unroll
        for (int kk = KW - 8; kk < KW; kk++) {
            ulonglong2 av = abuf[kk & 7];
            ulonglong2 b01 = *(const ulonglong2*)(bBase + kk * 16);
            ulonglong2 b23 = *(const ulonglong2*)(bBase + kk * 16 + 4);
            FMA2(acc2[0][0], av.x, b01.x); FMA2(acc2[0][1], av.y, b01.x);
            FMA2(acc2[1][0], av.x, b01.y); FMA2(acc2[1][1], av.y, b01.y);
            FMA2(acc2[2][0], av.x, b23.x); FMA2(acc2[2][1], av.y, b23.x);
            FMA2(acc2[3][0], av.x, b23.y); FMA2(acc2[3][1], av.y, b23.y);
        }

        // split-K reduction: packed-pair stores, NO pre-store sync needed
        // (this buffer was last read at step t-2; two barriers separate us)
        #pragma unroll
        for (int p = 0; p < 2; p++) {
            int base = ks * 256 + (m_thr * 2 + p) * 8 + n_thr * 4;
            ulonglong2 v01; v01.x = acc2[0][p]; v01.y = acc2[1][p];
            ulonglong2 v23; v23.x = acc2[2][p]; v23.y = acc2[3][p];
            *(ulonglong2*)&red2[base]     = v01;
            *(ulonglong2*)&red2[base + 2] = v23;
        }
        __syncthreads();

        // final sum (tid < 256): one m-pair each, LDS.64 + add.f32x2,
        // same p = 0..15 order as the old scalar sum -> bit-identical.
        if (tid < 256) {
            u64 s2 = red2[ep_red];
            #pragma unroll
            for (int p = 1; p < NWARP; p++) ADD2(s2, red2[p * 256 + ep_red]);
            float lo = __uint_as_float((unsigned)(s2 & 0xFFFFFFFFu));
            float hi = __uint_as_float((unsigned)(s2 >> 32));
            float v0 = tanhf(lo + bias + xp0);
            float v1 = tanhf(hi + bias + xp1);
            hx[ep_idx0] = v0;
            hx[ep_idx1] = v1;
            float2 hv; hv.x = v0; hv.y = v1;
            *(float2*)&hTo[ep_hT] = hv;
        }

        // grid barrier between steps (none after the last step)
        if (t < SS - 1) {
            __threadfence();
            __syncthreads();
            if (tid == 0) {
                unsigned old = atomicAdd(&g_bar[t], 1u);
                if (old != NB - 1) {
                    volatile unsigned* p = &g_bar[t];
                    while (*p < NB) { }
                }
            }
            __syncthreads();
        }
    }
}

// ============================================================================
// Launch: memset barriers -> xproj -> persistent RNN -> D2D h_last copy.
// ============================================================================
extern "C" void kernel_launch(void* const* d_in, const int* in_sizes, int n_in,
                              void* d_out, int out_size)
{
    const float* x  = (const float*)d_in[0];
    const float* Wx = (const float*)d_in[1];
    const float* bx = (const float*)d_in[2];
    const float* Wh = (const float*)d_in[3];
    const float* bh = (const float*)d_in[4];
    float* out = (float*)d_out;

    void* bar_ptr = nullptr;
    cudaGetSymbolAddress(&bar_ptr, g_bar);
    cudaMemsetAsync(bar_ptr, 0, SS * sizeof(unsigned));

    const int smemBytes = 16384 * 4 + 2 * 16 * 256 * 8;   // 64 KB + 64 KB = 128 KB
    cudaFuncSetAttribute(rnn_persistent,
                         cudaFuncAttributeMaxDynamicSharedMemorySize, smemBytes);

    xproj_kernel<<<dim3(HH / 64, (SS * BB) / 64), 256>>>(x, Wx, bx, out);
    rnn_persistent<<<NB, NTH, smemBytes>>>(Wh, bh, out);

    cudaMemcpyAsync(out + (size_t)SS * BH, out + (size_t)(SS - 1) * BH,
                    (size_t)BH * sizeof(float), cudaMemcpyDeviceToDevice);
}